// round 9
// baseline (speedup 1.0000x reference)
#include <cuda_runtime.h>
#include <cuda_bf16.h>
#include <cstdint>

// LayerHypercube: out[b, f*1024+o] = sum_j x[b, o^(1<<j)] * w[f,j,o] + bias[f,o] + x[b,o]
// B=2048, F=16, O=IN=1024, BITS=10. fm[f,j,o] == o^(1<<j) (computed, not loaded).
//
// R9: warp-private smem staging, no barriers (R8) + j=2..5 via LDS from own
// chunk (fewer issue slots than shfl) + ROWS=16 for wave smoothing.

#define BATCH   2048
#define INSZ    1024
#define OUTSZ   1024
#define NFM     16
#define NBITS   10

#define THREADS 128
#define NWARP   4
#define OG      16
#define OTILE   64
#define ROWS    16              // 8 pairs per block
#define PAIRS   (ROWS / 2)
#define OBLOCKS (OUTSZ / OTILE) // 16
#define BBLOCKS (BATCH / ROWS)  // 128
#define NBUF    3

#define CHUNK_B   256
#define ROW_B     (5 * CHUNK_B)     // 1280 bytes per row (5 chunks)
#define WBUF_B    (2 * ROW_B)       // 2560 bytes per warp-buffer (pair)

typedef unsigned long long ull;

__device__ __forceinline__ void cp16(uint32_t dst_smem, const void* src_gmem) {
    asm volatile("cp.async.cg.shared.global [%0], [%1], 16;\n"
                 :: "r"(dst_smem), "l"(src_gmem));
}
__device__ __forceinline__ void cp_commit() { asm volatile("cp.async.commit_group;\n"); }
__device__ __forceinline__ void cp_wait1()  { asm volatile("cp.async.wait_group 1;\n"); }

__device__ __forceinline__ void fma2(ull& d, ull a, ull b) {
    asm("fma.rn.f32x2 %0, %1, %2, %0;" : "+l"(d) : "l"(a), "l"(b));
}
__device__ __forceinline__ ull add2(ull a, ull b) {
    ull d; asm("add.rn.f32x2 %0, %1, %2;" : "=l"(d) : "l"(a), "l"(b)); return d;
}
__device__ __forceinline__ ull pk(float lo, float hi) {
    ull d; asm("mov.b64 %0, {%1, %2};" : "=l"(d) : "f"(lo), "f"(hi)); return d;
}
__device__ __forceinline__ void stcs2(void* p, ull lo, ull hi) {
    asm volatile("st.global.cs.v2.b64 [%0], {%1, %2};" :: "l"(p), "l"(lo), "l"(hi));
}

__global__ __launch_bounds__(THREADS, 4)
void hypercube_kernel(const float* __restrict__ x,
                      const float* __restrict__ w,
                      const float* __restrict__ bias,
                      float* __restrict__ out)
{
    __shared__ float4 sbuf[NBUF * NWARP * (WBUF_B / 16)];   // 30720 B

    const int tid   = threadIdx.x;
    const int lane  = tid & 31;
    const int wid   = tid >> 5;
    const int og    = tid & (OG - 1);
    const int fp    = tid >> 4;
    const int obase = blockIdx.x * OTILE + og * 4;
    const int row0  = blockIdx.y * ROWS;
    const int B0    = blockIdx.x * OTILE;

    // ---- weights & bias -> registers as f32x2 pairs ----
    ull w0l[NBITS], w0h[NBITS], w1l[NBITS], w1h[NBITS];
#pragma unroll
    for (int j = 0; j < NBITS; j++) {
        ulonglong2 t0 = *reinterpret_cast<const ulonglong2*>(
            w + ((fp * NBITS + j) * OUTSZ + obase));
        ulonglong2 t1 = *reinterpret_cast<const ulonglong2*>(
            w + (((fp + 8) * NBITS + j) * OUTSZ + obase));
        w0l[j] = t0.x; w0h[j] = t0.y;
        w1l[j] = t1.x; w1h[j] = t1.y;
    }
    const ulonglong2 bb0 = *reinterpret_cast<const ulonglong2*>(bias + fp * OUTSZ + obase);
    const ulonglong2 bb1 = *reinterpret_cast<const ulonglong2*>(bias + (fp + 8) * OUTSZ + obase);

    // ---- warp-private staging: 160 16B units per pair, 5 per lane ----
    int srcOff[5];
    {
        const int tb = B0 * 4;   // tile byte offset within a row
#pragma unroll
        for (int k = 0; k < 5; k++) {
            const int u = k * 32 + lane;
            const int r = (u >= 80) ? 1 : 0;
            const int t = u - 80 * r;
            const int c = t >> 4;
            const int i = t & 15;
            const int xorB = (c == 0) ? 0 : (256 << (c - 1));  // 0,256,512,1024,2048
            srcOff[k] = r * 4096 + (tb ^ xorB) + i * 16;
        }
    }

    const uint32_t wb0 = (uint32_t)__cvta_generic_to_shared(sbuf) + wid * WBUF_B;
    const char*    xpb = reinterpret_cast<const char*>(x + (size_t)row0 * INSZ);

    auto issue_pair = [&](int bufIdx, int pair) {
        const char* base = xpb + (size_t)pair * 8192;
        const uint32_t db = wb0 + bufIdx * (NWARP * WBUF_B) + lane * 16;
#pragma unroll
        for (int k = 0; k < 5; k++)
            cp16(db + k * 512, base + srcOff[k]);
    };

    issue_pair(0, 0); cp_commit();
    issue_pair(1, 1); cp_commit();

    float* op = out + (size_t)row0 * (NFM * OUTSZ) + fp * OUTSZ + obase;

    const int o1 = og ^ 1, o2 = og ^ 2, o4 = og ^ 4, o8 = og ^ 8;

    int cur = 0;
    for (int s = 0; s < PAIRS; s++) {
        cp_wait1();                       // warp-local: pair s landed

        int nxt = cur + 2; if (nxt >= NBUF) nxt -= NBUF;
        if (s + 2 < PAIRS) issue_pair(nxt, s + 2);
        cp_commit();

        const float4* rbA = sbuf + (cur * NWARP + wid) * (WBUF_B / 16);
        const float4* rbB = rbA + (ROW_B / 16);

        const float4 p = rbA[og];
        const float4 q = rbB[og];
        const ull Pl = pk(p.x, p.y), Ph = pk(p.z, p.w);
        const ull Ql = pk(q.x, q.y), Qh = pk(q.z, q.w);

        // acc = bias + tiled x
        ull a0l = add2(bb0.x, Pl), a0h = add2(bb0.y, Ph);
        ull a1l = add2(bb1.x, Pl), a1h = add2(bb1.y, Ph);
        ull c0l = add2(bb0.x, Ql), c0h = add2(bb0.y, Qh);
        ull c1l = add2(bb1.x, Ql), c1h = add2(bb1.y, Qh);

        // j=0: x[o^1] -> per-pair swap (free re-pack)
        {
            const ull Psl = pk(p.y, p.x), Psh = pk(p.w, p.z);
            const ull Qsl = pk(q.y, q.x), Qsh = pk(q.w, q.z);
            fma2(a0l, w0l[0], Psl); fma2(a0h, w0h[0], Psh);
            fma2(a1l, w1l[0], Psl); fma2(a1h, w1h[0], Psh);
            fma2(c0l, w0l[0], Qsl); fma2(c0h, w0h[0], Qsh);
            fma2(c1l, w1l[0], Qsl); fma2(c1h, w1h[0], Qsh);
        }

        // j=1: x[o^2] -> half reversal (operand order, free)
        fma2(a0l, w0l[1], Ph);  fma2(a0h, w0h[1], Pl);
        fma2(a1l, w1l[1], Ph);  fma2(a1h, w1h[1], Pl);
        fma2(c0l, w0l[1], Qh);  fma2(c0h, w0h[1], Ql);
        fma2(c1l, w1l[1], Qh);  fma2(c1h, w1h[1], Ql);

        // j=2..5: LDS from own chunk0 at og^{1,2,4,8} (one LDS.128 per j per row)
#pragma unroll
        for (int j = 2; j < 6; j++) {
            const int gi = (j == 2) ? o1 : (j == 3) ? o2 : (j == 4) ? o4 : o8;
            const ulonglong2 U = *reinterpret_cast<const ulonglong2*>(&rbA[gi]);
            const ulonglong2 V = *reinterpret_cast<const ulonglong2*>(&rbB[gi]);
            fma2(a0l, w0l[j], U.x); fma2(a0h, w0h[j], U.y);
            fma2(a1l, w1l[j], U.x); fma2(a1h, w1h[j], U.y);
            fma2(c0l, w0l[j], V.x); fma2(c0h, w0h[j], V.y);
            fma2(c1l, w1l[j], V.x); fma2(c1h, w1h[j], V.y);
        }

        // j=6..9: LDS gathers from chunks 1..4 at the SAME og (warp-own buffer)
#pragma unroll
        for (int j = 6; j < NBITS; j++) {
            const int gi = (j - 5) * 16 + og;
            const ulonglong2 U = *reinterpret_cast<const ulonglong2*>(&rbA[gi]);
            const ulonglong2 V = *reinterpret_cast<const ulonglong2*>(&rbB[gi]);
            fma2(a0l, w0l[j], U.x); fma2(a0h, w0h[j], U.y);
            fma2(a1l, w1l[j], U.x); fma2(a1h, w1h[j], U.y);
            fma2(c0l, w0l[j], V.x); fma2(c0h, w0h[j], V.y);
            fma2(c1l, w1l[j], V.x); fma2(c1h, w1h[j], V.y);
        }

        stcs2(op,                           a0l, a0h);
        stcs2(op + 8 * OUTSZ,               a1l, a1h);
        stcs2(op + NFM * OUTSZ,             c0l, c0h);
        stcs2(op + NFM * OUTSZ + 8 * OUTSZ, c1l, c1h);

        op += 2 * NFM * OUTSZ;
        cur = cur + 1; if (cur >= NBUF) cur -= NBUF;
    }
}

extern "C" void kernel_launch(void* const* d_in, const int* in_sizes, int n_in,
                              void* d_out, int out_size)
{
    const float* x    = (const float*)d_in[0];
    const float* w    = (const float*)d_in[1];
    const float* bias = (const float*)d_in[2];
    // d_in[3] = fm (int32) — values are o^(1<<j), computed inline instead.
    float* out = (float*)d_out;

    dim3 grid(OBLOCKS, BBLOCKS);
    hypercube_kernel<<<grid, THREADS>>>(x, w, bias, out);
}

// round 10
// speedup vs baseline: 1.0159x; 1.0159x over previous
#include <cuda_runtime.h>
#include <cuda_bf16.h>
#include <cstdint>

// LayerHypercube: out[b, f*1024+o] = sum_j x[b, o^(1<<j)] * w[f,j,o] + bias[f,o] + x[b,o]
// B=2048, F=16, O=IN=1024, BITS=10. fm[f,j,o] == o^(1<<j) (computed, not loaded).
//
// R10 = R8 (warp-private staging, no barriers, ROWS=32) +
//   - j=2..5: row A via shfl.bfly, row B via direct LDS (shorter dep chain)
//   - NBUF=4 with wait_group 2 (deeper cp.async pipeline)

#define BATCH   2048
#define INSZ    1024
#define OUTSZ   1024
#define NFM     16
#define NBITS   10

#define THREADS 128
#define NWARP   4
#define OG      16
#define OTILE   64
#define ROWS    32              // 16 pairs per block
#define PAIRS   (ROWS / 2)
#define OBLOCKS (OUTSZ / OTILE) // 16
#define BBLOCKS (BATCH / ROWS)  // 64
#define NBUF    4

#define CHUNK_B   256
#define ROW_B     (5 * CHUNK_B)     // 1280 bytes per row (5 chunks)
#define WBUF_B    (2 * ROW_B)       // 2560 bytes per warp-buffer (pair)

typedef unsigned long long ull;

__device__ __forceinline__ void cp16(uint32_t dst_smem, const void* src_gmem) {
    asm volatile("cp.async.cg.shared.global [%0], [%1], 16;\n"
                 :: "r"(dst_smem), "l"(src_gmem));
}
__device__ __forceinline__ void cp_commit() { asm volatile("cp.async.commit_group;\n"); }
__device__ __forceinline__ void cp_wait2()  { asm volatile("cp.async.wait_group 2;\n"); }

__device__ __forceinline__ void fma2(ull& d, ull a, ull b) {
    asm("fma.rn.f32x2 %0, %1, %2, %0;" : "+l"(d) : "l"(a), "l"(b));
}
__device__ __forceinline__ ull add2(ull a, ull b) {
    ull d; asm("add.rn.f32x2 %0, %1, %2;" : "=l"(d) : "l"(a), "l"(b)); return d;
}
__device__ __forceinline__ ull pk(float lo, float hi) {
    ull d; asm("mov.b64 %0, {%1, %2};" : "=l"(d) : "f"(lo), "f"(hi)); return d;
}
__device__ __forceinline__ void stcs2(void* p, ull lo, ull hi) {
    asm volatile("st.global.cs.v2.b64 [%0], {%1, %2};" :: "l"(p), "l"(lo), "l"(hi));
}

__global__ __launch_bounds__(THREADS, 4)
void hypercube_kernel(const float* __restrict__ x,
                      const float* __restrict__ w,
                      const float* __restrict__ bias,
                      float* __restrict__ out)
{
    __shared__ float4 sbuf[NBUF * NWARP * (WBUF_B / 16)];   // 40960 B

    const int tid   = threadIdx.x;
    const int lane  = tid & 31;
    const int wid   = tid >> 5;
    const int og    = tid & (OG - 1);
    const int fp    = tid >> 4;
    const int obase = blockIdx.x * OTILE + og * 4;
    const int row0  = blockIdx.y * ROWS;
    const int B0    = blockIdx.x * OTILE;

    // ---- weights & bias -> registers as f32x2 pairs ----
    ull w0l[NBITS], w0h[NBITS], w1l[NBITS], w1h[NBITS];
#pragma unroll
    for (int j = 0; j < NBITS; j++) {
        ulonglong2 t0 = *reinterpret_cast<const ulonglong2*>(
            w + ((fp * NBITS + j) * OUTSZ + obase));
        ulonglong2 t1 = *reinterpret_cast<const ulonglong2*>(
            w + (((fp + 8) * NBITS + j) * OUTSZ + obase));
        w0l[j] = t0.x; w0h[j] = t0.y;
        w1l[j] = t1.x; w1h[j] = t1.y;
    }
    const ulonglong2 bb0 = *reinterpret_cast<const ulonglong2*>(bias + fp * OUTSZ + obase);
    const ulonglong2 bb1 = *reinterpret_cast<const ulonglong2*>(bias + (fp + 8) * OUTSZ + obase);

    // ---- warp-private staging: 160 16B units per pair, 5 per lane ----
    int srcOff[5];
    {
        const int tb = B0 * 4;   // tile byte offset within a row
#pragma unroll
        for (int k = 0; k < 5; k++) {
            const int u = k * 32 + lane;
            const int r = (u >= 80) ? 1 : 0;
            const int t = u - 80 * r;
            const int c = t >> 4;
            const int i = t & 15;
            const int xorB = (c == 0) ? 0 : (256 << (c - 1));  // 0,256,512,1024,2048
            srcOff[k] = r * 4096 + (tb ^ xorB) + i * 16;
        }
    }

    const uint32_t wb0 = (uint32_t)__cvta_generic_to_shared(sbuf) + wid * WBUF_B;
    const char*    xpb = reinterpret_cast<const char*>(x + (size_t)row0 * INSZ);

    auto issue_pair = [&](int bufIdx, int pair) {
        const char* base = xpb + (size_t)pair * 8192;
        const uint32_t db = wb0 + bufIdx * (NWARP * WBUF_B) + lane * 16;
#pragma unroll
        for (int k = 0; k < 5; k++)
            cp16(db + k * 512, base + srcOff[k]);
    };

    issue_pair(0, 0); cp_commit();
    issue_pair(1, 1); cp_commit();
    issue_pair(2, 2); cp_commit();

    float* op = out + (size_t)row0 * (NFM * OUTSZ) + fp * OUTSZ + obase;

    const int o1 = og ^ 1, o2 = og ^ 2, o4 = og ^ 4, o8 = og ^ 8;

    int cur = 0;
    for (int s = 0; s < PAIRS; s++) {
        cp_wait2();                       // warp-local: pair s landed

        int nxt = cur + 3; if (nxt >= NBUF) nxt -= NBUF;
        if (s + 3 < PAIRS) issue_pair(nxt, s + 3);
        cp_commit();

        const float4* rbA = sbuf + (cur * NWARP + wid) * (WBUF_B / 16);
        const float4* rbB = rbA + (ROW_B / 16);

        const float4 p = rbA[og];
        const float4 q = rbB[og];
        const ull Pl = pk(p.x, p.y), Ph = pk(p.z, p.w);
        const ull Ql = pk(q.x, q.y), Qh = pk(q.z, q.w);

        // acc = bias + tiled x
        ull a0l = add2(bb0.x, Pl), a0h = add2(bb0.y, Ph);
        ull a1l = add2(bb1.x, Pl), a1h = add2(bb1.y, Ph);
        ull c0l = add2(bb0.x, Ql), c0h = add2(bb0.y, Qh);
        ull c1l = add2(bb1.x, Ql), c1h = add2(bb1.y, Qh);

        // j=0: x[o^1] -> per-pair swap (free re-pack)
        {
            const ull Psl = pk(p.y, p.x), Psh = pk(p.w, p.z);
            const ull Qsl = pk(q.y, q.x), Qsh = pk(q.w, q.z);
            fma2(a0l, w0l[0], Psl); fma2(a0h, w0h[0], Psh);
            fma2(a1l, w1l[0], Psl); fma2(a1h, w1h[0], Psh);
            fma2(c0l, w0l[0], Qsl); fma2(c0h, w0h[0], Qsh);
            fma2(c1l, w1l[0], Qsl); fma2(c1h, w1h[0], Qsh);
        }

        // j=1: x[o^2] -> half reversal (operand order, free)
        fma2(a0l, w0l[1], Ph);  fma2(a0h, w0h[1], Pl);
        fma2(a1l, w1l[1], Ph);  fma2(a1h, w1h[1], Pl);
        fma2(c0l, w0l[1], Qh);  fma2(c0h, w0h[1], Ql);
        fma2(c1l, w1l[1], Qh);  fma2(c1h, w1h[1], Ql);

        // j=2..5, row A: partner lane holds x[o^(4<<k)] -> shfl.bfly (p in regs)
        // j=2..5, row B: direct LDS.128 from own chunk0 (1-hop, shorter chain)
#pragma unroll
        for (int k = 0; k < 4; k++) {
            const int m = 1 << k;
            const int j = k + 2;
            const float ux = __shfl_xor_sync(0xffffffffu, p.x, m);
            const float uy = __shfl_xor_sync(0xffffffffu, p.y, m);
            const float uz = __shfl_xor_sync(0xffffffffu, p.z, m);
            const float uw = __shfl_xor_sync(0xffffffffu, p.w, m);
            const ull Ulo = pk(ux, uy), Uhi = pk(uz, uw);
            const int gi = (k == 0) ? o1 : (k == 1) ? o2 : (k == 2) ? o4 : o8;
            const ulonglong2 V = *reinterpret_cast<const ulonglong2*>(&rbB[gi]);
            fma2(a0l, w0l[j], Ulo); fma2(a0h, w0h[j], Uhi);
            fma2(a1l, w1l[j], Ulo); fma2(a1h, w1h[j], Uhi);
            fma2(c0l, w0l[j], V.x); fma2(c0h, w0h[j], V.y);
            fma2(c1l, w1l[j], V.x); fma2(c1h, w1h[j], V.y);
        }

        // j=6..9: LDS gathers from chunks 1..4 at the SAME og (warp-own buffer)
#pragma unroll
        for (int j = 6; j < NBITS; j++) {
            const int gi = (j - 5) * 16 + og;
            const ulonglong2 U = *reinterpret_cast<const ulonglong2*>(&rbA[gi]);
            const ulonglong2 V = *reinterpret_cast<const ulonglong2*>(&rbB[gi]);
            fma2(a0l, w0l[j], U.x); fma2(a0h, w0h[j], U.y);
            fma2(a1l, w1l[j], U.x); fma2(a1h, w1h[j], U.y);
            fma2(c0l, w0l[j], V.x); fma2(c0h, w0h[j], V.y);
            fma2(c1l, w1l[j], V.x); fma2(c1h, w1h[j], V.y);
        }

        stcs2(op,                           a0l, a0h);
        stcs2(op + 8 * OUTSZ,               a1l, a1h);
        stcs2(op + NFM * OUTSZ,             c0l, c0h);
        stcs2(op + NFM * OUTSZ + 8 * OUTSZ, c1l, c1h);

        op += 2 * NFM * OUTSZ;
        cur = cur + 1; if (cur >= NBUF) cur -= NBUF;
    }
}

extern "C" void kernel_launch(void* const* d_in, const int* in_sizes, int n_in,
                              void* d_out, int out_size)
{
    const float* x    = (const float*)d_in[0];
    const float* w    = (const float*)d_in[1];
    const float* bias = (const float*)d_in[2];
    // d_in[3] = fm (int32) — values are o^(1<<j), computed inline instead.
    float* out = (float*)d_out;

    dim3 grid(OBLOCKS, BBLOCKS);
    hypercube_kernel<<<grid, THREADS>>>(x, w, bias, out);
}